// round 9
// baseline (speedup 1.0000x reference)
#include <cuda_runtime.h>
#include <math.h>

#define T_LEN    8192
#define NDELAY   360
#define NTHREADS 512
#define SPAD     160
#define FULLMASK 0xffffffffu

// ---------------------------------------------------------------------------
// y_t = x_t - a1*y_{t-L1} - a2*y_{t-L2}; exactly two taps (straight-through
// one-hot is exactly hard in fp32), L1 = 61+m, L2 = 61+((m+1)%360).
// Typical case m != 359: L2 = L1+1. Chunk width C = L1:
//   tap1 (lag L1)   -> previous round, SAME register slot (register carry)
//   tap2 (lag L1+1) -> previous round shifted by 1      (__shfl_up)
// Single warp, zero barriers. This round: branch-free stores (single-compare
// predicates only), software-pipelined LDS prefetch, countable unrolled loop,
// peeled final partial round -> critical path ~= shfl(26)+SEL+2*FMA.
// ---------------------------------------------------------------------------

__device__ __forceinline__ float tanh_fast(float x) {
    x = fminf(fmaxf(x, -15.0f), 15.0f);
    float e = __expf(2.0f * x);
    return (e - 1.0f) * __frcp_rn(e + 1.0f);
}

template <int Q>
__device__ __forceinline__ void serial_fast(const float* __restrict__ A,
                                            float* __restrict__ yr,
                                            float a1, float a2, int C) {
    const int lane  = threadIdx.x & 31;
    const int lt    = (C - 1) & 31;        // lane of last element in reg Q-1
    const int lastN = C - 32 * (Q - 1);    // valid lanes in last register
    const bool lastOk = lane < lastN;

    const int nfull = T_LEN / C;           // complete rounds (incl. round 0)
    const int rem   = T_LEN - nfull * C;   // final partial round width

    // --- round 0: y = x on [0, C) (all lags >= C) ---
    float yp[Q];
#pragma unroll
    for (int j = 0; j < Q; j++) yp[j] = A[32 * j + lane];
#pragma unroll
    for (int j = 0; j < Q - 1; j++) yr[32 * j + lane] = yp[j];
    if (lastOk) yr[32 * (Q - 1) + lane] = yp[Q - 1];

    float tailA = __shfl_sync(FULLMASK, yp[Q - 1], lt);  // y_{r-1}[C-1]
    float tailB = 0.0f;                                  // y_{r-2}[C-1]

    // prefetch centers for round 1
    float cxp[Q];
#pragma unroll
    for (int j = 0; j < Q; j++) cxp[j] = A[C + 32 * j + lane];

    int s0 = C;
#pragma unroll 2
    for (int r = 1; r < nfull; r++) {
        // prefetch next round's centers (pad makes the tail reads safe)
        float cxn[Q];
#pragma unroll
        for (int j = 0; j < Q; j++) cxn[j] = A[s0 + C + 32 * j + lane];

        // boundary values: lane 31 of each register (feeds register j+1)
        float b31[Q];
#pragma unroll
        for (int j = 0; j < Q - 1; j++) b31[j] = __shfl_sync(FULLMASK, yp[j], 31);

        float yn[Q];
#pragma unroll
        for (int j = 0; j < Q; j++) {
            float u = __shfl_up_sync(FULLMASK, yp[j], 1);
            float bv = (j == 0) ? tailB : b31[j - 1];
            u = (lane == 0) ? bv : u;
            yn[j] = fmaf(-a2, u, fmaf(-a1, yp[j], cxp[j]));
        }
        tailB = tailA;
        tailA = __shfl_sync(FULLMASK, yn[Q - 1], lt);

        // stores: all registers unconditional except the partial last one
#pragma unroll
        for (int j = 0; j < Q - 1; j++) yr[s0 + 32 * j + lane] = yn[j];
        if (lastOk) yr[s0 + 32 * (Q - 1) + lane] = yn[Q - 1];

#pragma unroll
        for (int j = 0; j < Q; j++) { yp[j] = yn[j]; cxp[j] = cxn[j]; }
        s0 += C;
    }

    // --- peeled final partial round [nfull*C, T_LEN), width rem < C ---
    if (rem > 0) {
#pragma unroll
        for (int j = 0; j < Q; j++) {
            float u = __shfl_up_sync(FULLMASK, yp[j], 1);
            float bj = (j == 0) ? tailB
                                : __shfl_sync(FULLMASK, yp[j - 1], 31);
            u = (lane == 0) ? bj : u;
            float yv = fmaf(-a2, u, fmaf(-a1, yp[j], cxp[j]));
            const int p = 32 * j + lane;
            if (p < rem) yr[s0 + p] = yv;
        }
    }
}

__global__ void __launch_bounds__(NTHREADS, 1)
ks_fused_kernel(const float* __restrict__ x,
                const float* __restrict__ gumbel,
                const float* __restrict__ delayp,
                const float* __restrict__ fb,
                const float* __restrict__ rc,
                float* __restrict__ out) {
    extern __shared__ float A[];        // [T_LEN + SPAD]

    __shared__ float s_rv[16];
    __shared__ int   s_ri[16];
    __shared__ int   s_m;

    const int tid  = threadIdx.x;
    const int row  = blockIdx.x;
    const int lane = tid & 31;
    const int wid  = tid >> 5;
    const float* xr = x + (size_t)row * T_LEN;
    float*       yr = out + (size_t)row * T_LEN;

    // --- stage x into smem (coalesced float4), zero the tail pad ---
    {
        const float4* x4 = (const float4*)xr;
        float4* a4 = (float4*)A;
#pragma unroll
        for (int i = 0; i < T_LEN / 4 / NTHREADS; i++)
            a4[tid + i * NTHREADS] = x4[tid + i * NTHREADS];
        if (tid < SPAD) A[T_LEN + tid] = 0.0f;
    }

    // --- argmax over 360 logits (first-index tie-break) ---
    float lv = -INFINITY;
    int   li = tid;
    if (tid < NDELAY) lv = delayp[tid] + gumbel[tid];
#pragma unroll
    for (int off = 16; off > 0; off >>= 1) {
        float ov = __shfl_down_sync(FULLMASK, lv, off);
        int   oi = __shfl_down_sync(FULLMASK, li, off);
        if (ov > lv || (ov == lv && oi < li)) { lv = ov; li = oi; }
    }
    if (lane == 0) { s_rv[wid] = lv; s_ri[wid] = li; }

    // --- scalar coefficients (redundant per thread; fast intrinsics) ---
    float k1 = tanh_fast(tanh_fast(rc[0]));
    float k2 = tanh_fast(tanh_fast(rc[1]));
    float a1 = k1 * (1.0f - k2);
    float a2 = fminf(fmaxf(k2, -0.999f), 0.999f);
    float bound = 0.999f - fabsf(a2);
    a1 = fminf(fmaxf(a1, -bound), bound);
    float sg = __frcp_rn(1.0f + __expf(-fb[0]));
    float g  = __powf(sg, 0.45f);
    a1 *= g;
    a2 *= g;

    __syncthreads();
    if (tid < 32) {
        lv = (lane < 16) ? s_rv[lane] : -INFINITY;
        li = (lane < 16) ? s_ri[lane] : 0x7fffffff;
#pragma unroll
        for (int off = 8; off > 0; off >>= 1) {
            float ov = __shfl_down_sync(FULLMASK, lv, off);
            int   oi = __shfl_down_sync(FULLMASK, li, off);
            if (ov > lv || (ov == lv && oi < li)) { lv = ov; li = oi; }
        }
        if (lane == 0) s_m = li;
    }
    __syncthreads();   // staging + argmax complete

    const int m  = s_m;
    const int L1 = 61 + m;
    const int L2 = 61 + ((m + 1) % NDELAY);
    const int C  = (L1 < L2) ? L1 : L2;

    const bool fast = (L2 == L1 + 1) && (L1 <= 128);

    if (fast) {
        if (wid != 0) return;           // helpers exit
        const int Q = (C + 31) >> 5;    // 2..4
        if (Q == 2)      serial_fast<2>(A, yr, a1, a2, C);
        else if (Q == 3) serial_fast<3>(A, yr, a1, a2, C);
        else             serial_fast<4>(A, yr, a1, a2, C);
        return;
    }

    // --- fallback: barrier rounds, width C, all threads (rare path) ---
    {
        for (int t = tid; t < C; t += NTHREADS) yr[t] = A[t];
        for (int s0 = C; s0 < T_LEN; s0 += C) {
            __syncthreads();
            const int end = (s0 + C < T_LEN) ? (s0 + C) : T_LEN;
            for (int t = s0 + tid; t < end; t += NTHREADS) {
                float v1 = (t >= L1) ? A[t - L1] : 0.0f;
                float v2 = (t >= L2) ? A[t - L2] : 0.0f;
                float y = A[t] - a1 * v1 - a2 * v2;
                A[t] = y;
                yr[t] = y;
            }
        }
    }
}

// ---------------------------------------------------------------------------
// inputs: excitation[128*8192] f32, gumbel[360], delay_param[360],
//         feedback_gain[1], reflection_coeffs[2]; output f32 [128*8192]
// ---------------------------------------------------------------------------
extern "C" void kernel_launch(void* const* d_in, const int* in_sizes, int n_in,
                              void* d_out, int out_size) {
    const float* x      = (const float*)d_in[0];
    const float* gumbel = (const float*)d_in[1];
    const float* delayp = (const float*)d_in[2];
    const float* fb     = (const float*)d_in[3];
    const float* rc     = (const float*)d_in[4];
    float* out = (float*)d_out;

    const int rows = in_sizes[0] / T_LEN;
    const int smem_bytes = (T_LEN + SPAD) * sizeof(float);

    cudaFuncSetAttribute(ks_fused_kernel,
                         cudaFuncAttributeMaxDynamicSharedMemorySize, smem_bytes);
    ks_fused_kernel<<<rows, NTHREADS, smem_bytes>>>(x, gumbel, delayp, fb, rc, out);
}

// round 10
// speedup vs baseline: 1.1017x; 1.1017x over previous
#include <cuda_runtime.h>
#include <math.h>

#define T_LEN    8192
#define NDELAY   360
#define NTHREADS 512
#define TPAD     448            // 32*14: max over-read/over-write past T_LEN
#define FULLMASK 0xffffffffu

// ---------------------------------------------------------------------------
// y_t = x_t - a1*y_{t-L1} - a2*y_{t-L2}; exactly two taps (straight-through
// one-hot is exactly hard in fp32), L1 = 61+m, L2 = 61+((m+1)%360).
// For m != 359 (evidence: true for this dataset): L2 = L1+1.
// Serial phase in ONE warp, round width C = L1, lane-major register layout:
//   slot p = lane*Q + j  (Q = ceil(C/32) registers per lane)
//   tap1 (lag C)   -> same slot, previous round      (register)
//   tap2 (lag C+1) -> slot p-1, previous round:
//        j>0 : yp[j-1]               (register move, free)
//        j==0: shfl_up(yp[Q-1], 1)   (one shuffle per round)
//        lane0/j0: tail of round r-2 (carried broadcast)
// No barriers, no predicates in the loop (out-of-range slots compute garbage
// that later rounds overwrite in program order). Results go to smem; one
// final barrier + all-warp float4 writeback.
// ---------------------------------------------------------------------------

__device__ __forceinline__ float tanh_fast(float x) {
    x = fminf(fmaxf(x, -15.0f), 15.0f);
    float e = __expf(2.0f * x);
    return (e - 1.0f) * __frcp_rn(e + 1.0f);
}

template <int Q>
__device__ __forceinline__ void serial_lm(const float* __restrict__ A,
                                          float* __restrict__ Y,
                                          float a1, float a2, int C) {
    const int lane = threadIdx.x & 31;
    const int base = lane * Q;
    const int lt   = (C - 1) / Q;     // lane holding slot C-1 (uniform)
    const int jt   = (C - 1) % Q;     // register holding slot C-1 (uniform)
    const int nrounds = (T_LEN + C - 1) / C;

    // round 0: y = x on [0, C)  (all lags >= C)
    float yp[Q];
#pragma unroll
    for (int j = 0; j < Q; j++) yp[j] = A[base + j];
#pragma unroll
    for (int j = 0; j < Q; j++) Y[base + j] = yp[j];

    // tail of round 0: y[C-1]
    float v = yp[0];
#pragma unroll
    for (int j = 1; j < Q; j++) v = (jt == j) ? yp[j] : v;
    float tailA = __shfl_sync(FULLMASK, v, lt);   // y[r-1 tail]
    float tailB = 0.0f;                           // y[r-2 tail]

    int s0 = C;
    for (int r = 1; r < nrounds; r++) {
        // centers: LDS latency overlaps the shuffle (taps are registers)
        float cx[Q];
#pragma unroll
        for (int j = 0; j < Q; j++) cx[j] = A[s0 + base + j];

        float up = __shfl_up_sync(FULLMASK, yp[Q - 1], 1);
        up = (lane == 0) ? tailB : up;

        float yn[Q];
#pragma unroll
        for (int j = 0; j < Q; j++) {
            float t2 = (j == 0) ? up : yp[j - 1];
            yn[j] = fmaf(-a2, t2, fmaf(-a1, yp[j], cx[j]));
        }

        // unconditional stores; invalid slots are overwritten by later rounds
#pragma unroll
        for (int j = 0; j < Q; j++) Y[s0 + base + j] = yn[j];

        // next tail (needed two rounds later -> off critical path)
        float w = yn[0];
#pragma unroll
        for (int j = 1; j < Q; j++) w = (jt == j) ? yn[j] : w;
        tailB = tailA;
        tailA = __shfl_sync(FULLMASK, w, lt);

#pragma unroll
        for (int j = 0; j < Q; j++) yp[j] = yn[j];
        s0 += C;
    }
}

__global__ void __launch_bounds__(NTHREADS, 1)
ks_fused_kernel(const float* __restrict__ x,
                const float* __restrict__ gumbel,
                const float* __restrict__ delayp,
                const float* __restrict__ fb,
                const float* __restrict__ rc,
                float* __restrict__ out) {
    extern __shared__ float smem[];
    float* A = smem;                        // x staged, [T_LEN + TPAD]
    float* Y = smem + T_LEN + TPAD;         // y result, [T_LEN + TPAD]

    __shared__ float s_rv[16];
    __shared__ int   s_ri[16];
    __shared__ int   s_m;

    const int tid  = threadIdx.x;
    const int row  = blockIdx.x;
    const int lane = tid & 31;
    const int wid  = tid >> 5;
    const float* xr = x + (size_t)row * T_LEN;
    float*       yr = out + (size_t)row * T_LEN;

    // --- stage x into smem (coalesced float4), zero A's tail pad ---
    {
        const float4* x4 = (const float4*)xr;
        float4* a4 = (float4*)A;
#pragma unroll
        for (int i = 0; i < T_LEN / 4 / NTHREADS; i++)
            a4[tid + i * NTHREADS] = x4[tid + i * NTHREADS];
        if (tid < TPAD) A[T_LEN + tid] = 0.0f;
    }

    // --- argmax over 360 logits (first-index tie-break) ---
    float lv = -INFINITY;
    int   li = tid;
    if (tid < NDELAY) lv = delayp[tid] + gumbel[tid];
#pragma unroll
    for (int off = 16; off > 0; off >>= 1) {
        float ov = __shfl_down_sync(FULLMASK, lv, off);
        int   oi = __shfl_down_sync(FULLMASK, li, off);
        if (ov > lv || (ov == lv && oi < li)) { lv = ov; li = oi; }
    }
    if (lane == 0) { s_rv[wid] = lv; s_ri[wid] = li; }

    // --- scalar coefficients (redundant per thread; fast intrinsics) ---
    float k1 = tanh_fast(tanh_fast(rc[0]));
    float k2 = tanh_fast(tanh_fast(rc[1]));
    float a1 = k1 * (1.0f - k2);
    float a2 = fminf(fmaxf(k2, -0.999f), 0.999f);
    float bound = 0.999f - fabsf(a2);
    a1 = fminf(fmaxf(a1, -bound), bound);
    float sg = __frcp_rn(1.0f + __expf(-fb[0]));
    float g  = __powf(sg, 0.45f);
    a1 *= g;
    a2 *= g;

    __syncthreads();
    if (tid < 32) {
        lv = (lane < 16) ? s_rv[lane] : -INFINITY;
        li = (lane < 16) ? s_ri[lane] : 0x7fffffff;
#pragma unroll
        for (int off = 8; off > 0; off >>= 1) {
            float ov = __shfl_down_sync(FULLMASK, lv, off);
            int   oi = __shfl_down_sync(FULLMASK, li, off);
            if (ov > lv || (ov == lv && oi < li)) { lv = ov; li = oi; }
        }
        if (lane == 0) s_m = li;
    }
    __syncthreads();   // staging + argmax complete

    const int m  = s_m;
    const int L1 = 61 + m;
    const int L2 = 61 + ((m + 1) % NDELAY);
    const int C  = (L1 < L2) ? L1 : L2;

    if (L2 == L1 + 1) {
        // --- single-warp serial phase, lane-major registers ---
        if (wid == 0) {
            switch ((C + 31) >> 5) {     // Q = 2..14
                case 2:  serial_lm<2>(A, Y, a1, a2, C);  break;
                case 3:  serial_lm<3>(A, Y, a1, a2, C);  break;
                case 4:  serial_lm<4>(A, Y, a1, a2, C);  break;
                case 5:  serial_lm<5>(A, Y, a1, a2, C);  break;
                case 6:  serial_lm<6>(A, Y, a1, a2, C);  break;
                case 7:  serial_lm<7>(A, Y, a1, a2, C);  break;
                case 8:  serial_lm<8>(A, Y, a1, a2, C);  break;
                case 9:  serial_lm<9>(A, Y, a1, a2, C);  break;
                case 10: serial_lm<10>(A, Y, a1, a2, C); break;
                case 11: serial_lm<11>(A, Y, a1, a2, C); break;
                case 12: serial_lm<12>(A, Y, a1, a2, C); break;
                case 13: serial_lm<13>(A, Y, a1, a2, C); break;
                default: serial_lm<14>(A, Y, a1, a2, C); break;
            }
        }
        __syncthreads();
        // all-warp vectorized writeback
        float4* o4 = (float4*)yr;
        const float4* y4 = (const float4*)Y;
#pragma unroll
        for (int i = 0; i < T_LEN / 4 / NTHREADS; i++)
            o4[tid + i * NTHREADS] = y4[tid + i * NTHREADS];
        return;
    }

    // --- fallback (m == 359 only): barrier rounds, width C ---
    {
        for (int t = tid; t < C; t += NTHREADS) yr[t] = A[t];
        for (int s0 = C; s0 < T_LEN; s0 += C) {
            __syncthreads();
            const int end = (s0 + C < T_LEN) ? (s0 + C) : T_LEN;
            for (int t = s0 + tid; t < end; t += NTHREADS) {
                float v1 = (t >= L1) ? A[t - L1] : 0.0f;
                float v2 = (t >= L2) ? A[t - L2] : 0.0f;
                float y = A[t] - a1 * v1 - a2 * v2;
                A[t] = y;
                yr[t] = y;
            }
        }
    }
}

// ---------------------------------------------------------------------------
// inputs: excitation[128*8192] f32, gumbel[360], delay_param[360],
//         feedback_gain[1], reflection_coeffs[2]; output f32 [128*8192]
// ---------------------------------------------------------------------------
extern "C" void kernel_launch(void* const* d_in, const int* in_sizes, int n_in,
                              void* d_out, int out_size) {
    const float* x      = (const float*)d_in[0];
    const float* gumbel = (const float*)d_in[1];
    const float* delayp = (const float*)d_in[2];
    const float* fb     = (const float*)d_in[3];
    const float* rc     = (const float*)d_in[4];
    float* out = (float*)d_out;

    const int rows = in_sizes[0] / T_LEN;
    const int smem_bytes = 2 * (T_LEN + TPAD) * sizeof(float);

    cudaFuncSetAttribute(ks_fused_kernel,
                         cudaFuncAttributeMaxDynamicSharedMemorySize, smem_bytes);
    ks_fused_kernel<<<rows, NTHREADS, smem_bytes>>>(x, gumbel, delayp, fb, rc, out);
}